// round 1
// baseline (speedup 1.0000x reference)
#include <cuda_runtime.h>
#include <math.h>
#include <stdint.h>

// ---------------------------------------------------------------------------
// GraphProjection: 80000 points, 3 cameras, 4 feature pyramids (64/128/256/512 ch)
// out[p] = [coord(3) | max over views(960) | mean(960) | std(960)]  -> 2883 f32
//
// Reference quirk replicated: idx[:,0] = int32(view / (224/d)) == 0 for all
// views/scales, so every gather reads batch 0 of each feature tensor.
// ---------------------------------------------------------------------------

#define MAX_N 80000
#define OUT_STRIDE 2883

struct CamData {
    float B0[9];     // inv(c0^T), used as po_j = sum_k coord_k * B0[k*3+j] + o0_j
    float c[3][9];   // per-view rotation rows (X,Y,Z normalized)
    float o[3][3];   // per-view camera origin (unnormalized Z)
};

__device__ CamData g_cam;
__device__ int g_off[MAX_N * 12];   // [point][view*4 + scale] flat float offset

// --- camera matrix, mirroring jnp fp32 op order -----------------------------
__device__ void cam_mat(const float* prm, float* Crow, float* O) {
    const float PI = 3.14159265358979323846f;
    float theta = prm[0] * PI / 180.0f;
    float e     = prm[1] * PI / 180.0f;
    float camy  = prm[3] * sinf(e);
    float lens  = prm[3] * cosf(e);
    float camx  = lens * cosf(theta);
    float camz  = lens * sinf(theta);

    float Zv[3] = { camx, camy, camz };
    float Yv[3] = { camy * cosf(theta + PI), lens, camy * sinf(theta + PI) };
    // X = cross(Y, Z)
    float Xv[3] = { Yv[1]*Zv[2] - Yv[2]*Zv[1],
                    Yv[2]*Zv[0] - Yv[0]*Zv[2],
                    Yv[0]*Zv[1] - Yv[1]*Zv[0] };

    float nx = sqrtf(Xv[0]*Xv[0] + Xv[1]*Xv[1] + Xv[2]*Xv[2]);
    float ny = sqrtf(Yv[0]*Yv[0] + Yv[1]*Yv[1] + Yv[2]*Yv[2]);
    float nz = sqrtf(Zv[0]*Zv[0] + Zv[1]*Zv[1] + Zv[2]*Zv[2]);
    for (int k = 0; k < 3; k++) {
        Crow[0*3 + k] = __fdiv_rn(Xv[k], nx);
        Crow[1*3 + k] = __fdiv_rn(Yv[k], ny);
        Crow[2*3 + k] = __fdiv_rn(Zv[k], nz);
        O[k] = Zv[k];
    }
}

__global__ void setup_cams(const float* __restrict__ cams) {
    if (threadIdx.x != 0) return;
    for (int i = 0; i < 3; i++)
        cam_mat(cams + i * 5, g_cam.c[i], g_cam.o[i]);

    // B0 = inv(c0^T), via double-precision cofactors of the fp32 matrix.
    double M[3][3];
    for (int r = 0; r < 3; r++)
        for (int k = 0; k < 3; k++)
            M[r][k] = (double)g_cam.c[0][k*3 + r];   // c0^T

    double det = M[0][0]*(M[1][1]*M[2][2] - M[1][2]*M[2][1])
               - M[0][1]*(M[1][0]*M[2][2] - M[1][2]*M[2][0])
               + M[0][2]*(M[1][0]*M[2][1] - M[1][1]*M[2][0]);
    double inv[3][3];
    inv[0][0] =  (M[1][1]*M[2][2] - M[1][2]*M[2][1]) / det;
    inv[0][1] =  (M[0][2]*M[2][1] - M[0][1]*M[2][2]) / det;
    inv[0][2] =  (M[0][1]*M[1][2] - M[0][2]*M[1][1]) / det;
    inv[1][0] =  (M[1][2]*M[2][0] - M[1][0]*M[2][2]) / det;
    inv[1][1] =  (M[0][0]*M[2][2] - M[0][2]*M[2][0]) / det;
    inv[1][2] =  (M[0][2]*M[1][0] - M[0][0]*M[1][2]) / det;
    inv[2][0] =  (M[1][0]*M[2][1] - M[1][1]*M[2][0]) / det;
    inv[2][1] =  (M[0][1]*M[2][0] - M[0][0]*M[2][1]) / det;
    inv[2][2] =  (M[0][0]*M[1][1] - M[0][1]*M[1][0]) / det;
    for (int k = 0; k < 3; k++)
        for (int j = 0; j < 3; j++)
            g_cam.B0[k*3 + j] = (float)inv[k][j];
}

// --- per-point projection -> 12 gather offsets + coord passthrough ----------
__global__ void compute_off(const float* __restrict__ coord,
                            float* __restrict__ out, int N) {
    int p = blockIdx.x * blockDim.x + threadIdx.x;
    if (p >= N) return;

    float x = coord[p*3 + 0];
    float y = coord[p*3 + 1];
    float z = coord[p*3 + 2];

    // point_origin = coord @ inv(c0^T) + o0
    float po[3];
    #pragma unroll
    for (int j = 0; j < 3; j++)
        po[j] = x * g_cam.B0[0*3 + j] + y * g_cam.B0[1*3 + j]
              + z * g_cam.B0[2*3 + j] + g_cam.o[0][j];

    float* op = out + (size_t)p * OUT_STRIDE;
    op[0] = x; op[1] = y; op[2] = z;

    const int   ds[4] = { 56, 28, 14, 7 };
    const int   Cs[4] = { 64, 128, 256, 512 };
    const float qi[4] = { 0.25f, 0.125f, 0.0625f, 0.03125f };  // d/224, exact pow2

    #pragma unroll
    for (int i = 0; i < 3; i++) {
        float vx = po[0] - g_cam.o[i][0];
        float vy = po[1] - g_cam.o[i][1];
        float vz = po[2] - g_cam.o[i][2];
        const float* C = g_cam.c[i];
        float X  = vx*C[0] + vy*C[1] + vz*C[2];
        float Y  = vx*C[3] + vy*C[4] + vz*C[5];
        float Zc = vx*C[6] + vy*C[7] + vz*C[8];

        float negz = -Zc;
        float h = __fdiv_rn(248.0f * (-Y), negz) + 112.0f;
        float w = __fdiv_rn(248.0f * X,    negz) + 112.0f;
        h = fminf(fmaxf(h, 0.0f), 223.0f);
        w = fminf(fmaxf(w, 0.0f), 223.0f);

        #pragma unroll
        for (int s = 0; s < 4; s++) {
            int ih = (int)(h * qi[s]);
            int iw = (int)(w * qi[s]);
            g_off[p*12 + i*4 + s] = (ih * ds[s] + iw) * Cs[s];
        }
    }
}

// --- main gather + per-channel stats: block = point, thread = channel -------
__global__ __launch_bounds__(960)
void gather_kernel(const float* __restrict__ f1, const float* __restrict__ f2,
                   const float* __restrict__ f3, const float* __restrict__ f4,
                   float* __restrict__ out) {
    int p = blockIdx.x;
    int c = threadIdx.x;

    __shared__ int soff[12];
    if (c < 12) soff[c] = g_off[p*12 + c];
    __syncthreads();

    const float* f;
    int cl, s;
    if (c < 64)       { s = 0; f = f1; cl = c; }
    else if (c < 192) { s = 1; f = f2; cl = c - 64; }
    else if (c < 448) { s = 2; f = f3; cl = c - 192; }
    else              { s = 3; f = f4; cl = c - 448; }

    float a = __ldg(f + soff[0 + s] + cl);
    float b = __ldg(f + soff[4 + s] + cl);
    float d = __ldg(f + soff[8 + s] + cl);

    float mx = fmaxf(a, fmaxf(b, d));
    float mn = (a + b + d) * (1.0f / 3.0f);
    float da = a - mn, db = b - mn, dc = d - mn;
    float sd = sqrtf((da*da + db*db + dc*dc) * (1.0f / 3.0f));

    float* op = out + (size_t)p * OUT_STRIDE;
    op[3 + c]    = mx;
    op[963 + c]  = mn;
    op[1923 + c] = sd;
}

extern "C" void kernel_launch(void* const* d_in, const int* in_sizes, int n_in,
                              void* d_out, int out_size) {
    const float* coord = (const float*)d_in[0];
    const float* cams  = (const float*)d_in[1];
    const float* f1    = (const float*)d_in[2];
    const float* f2    = (const float*)d_in[3];
    const float* f3    = (const float*)d_in[4];
    const float* f4    = (const float*)d_in[5];
    float* out = (float*)d_out;

    int N = in_sizes[0] / 3;

    setup_cams<<<1, 32>>>(cams);
    compute_off<<<(N + 255) / 256, 256>>>(coord, out, N);
    gather_kernel<<<N, 960>>>(f1, f2, f3, f4, out);
}